// round 15
// baseline (speedup 1.0000x reference)
#include <cuda_runtime.h>
#include <cstdint>

// CausalConv1d: x (4, 2048, 8192) f32, depthwise weight (2048, 1, 16), bias (2048)
// out[n,c,l] = sum_{k=0..15} x[n,c,l-15+k] * w[c,0,k] + bias[c]   (zero-pad left)
//
// R14 + contiguous row buffer: smem holds buf[16 + 8192] so the 8 per-stage
// cp.async.bulk transfers are exactly 4KB, aligned, with NO halo overlap.
// Stage s's halo is the tail of stage s-1's region (already resident; stages
// are consumed in order so barrier s-1 was waited before stage s). Saves the
// 1.4% duplicated halo read traffic and the misaligned 4160B transfers.
// Everything else identical: warp s issues stage s (evict_first L2 hint),
// 5 conflict-free LDS.128 + 64 FMA + st.global.cs per stage, 5 blocks/SM.

#define DIM    2048
#define LEN    8192
#define KSZ    16
#define BLOCK  256
#define OPT    4
#define TILE   (BLOCK * OPT)      // 1024
#define NST    (LEN / TILE)       // 8 stages
#define TILEB  (TILE * 4)         // 4096 bytes per stage transfer

__device__ __forceinline__ uint32_t smem_u32(const void* p) {
    return (uint32_t)__cvta_generic_to_shared(p);
}

__device__ __forceinline__ void mbar_init(uint32_t mbar, uint32_t count) {
    asm volatile("mbarrier.init.shared.b64 [%0], %1;" :: "r"(mbar), "r"(count) : "memory");
}

__device__ __forceinline__ void mbar_expect_tx(uint32_t mbar, uint32_t bytes) {
    asm volatile("mbarrier.arrive.expect_tx.shared.b64 _, [%0], %1;"
                 :: "r"(mbar), "r"(bytes) : "memory");
}

__device__ __forceinline__ uint64_t l2_evict_first_policy() {
    uint64_t pol;
    asm("createpolicy.fractional.L2::evict_first.b64 %0, 1.0;" : "=l"(pol));
    return pol;
}

__device__ __forceinline__ void bulk_g2s_hint(uint32_t dst, const void* src,
                                              uint32_t bytes, uint32_t mbar,
                                              uint64_t pol) {
    asm volatile(
        "cp.async.bulk.shared::cta.global.mbarrier::complete_tx::bytes.L2::cache_hint"
        " [%0], [%1], %2, [%3], %4;"
        :: "r"(dst), "l"(src), "r"(bytes), "r"(mbar), "l"(pol) : "memory");
}

__device__ __forceinline__ void mbar_wait_parity0(uint32_t mbar) {
    uint32_t done;
    asm volatile(
        "{\n\t.reg .pred p;\n\t"
        "mbarrier.try_wait.parity.acquire.cta.shared::cta.b64 p, [%1], 0;\n\t"
        "selp.b32 %0, 1, 0, p;\n\t}"
        : "=r"(done) : "r"(mbar) : "memory");
    if (!done) {
        asm volatile(
            "{\n\t.reg .pred P1;\n\t"
            "WAIT_LOOP_%=:\n\t"
            "mbarrier.try_wait.parity.acquire.cta.shared::cta.b64 P1, [%0], 0, 0x989680;\n\t"
            "@P1 bra.uni WAIT_DONE_%=;\n\t"
            "bra.uni WAIT_LOOP_%=;\n\t"
            "WAIT_DONE_%=:\n\t}"
            :: "r"(mbar) : "memory");
    }
}

__device__ __forceinline__ void stg_cs_v4(float* p, float a, float b, float c, float d) {
    asm volatile("st.global.cs.v4.f32 [%0], {%1, %2, %3, %4};"
                 :: "l"(p), "f"(a), "f"(b), "f"(c), "f"(d) : "memory");
}

__global__ __launch_bounds__(BLOCK, 5) void causal_conv1d_kernel(
    const float* __restrict__ x,
    const float* __restrict__ w,
    const float* __restrict__ bias,
    float* __restrict__ out)
{
    // buf[16 + i] = xrow[i]; buf[0:16] = zero left pad (never overwritten)
    __shared__ alignas(128) float buf[KSZ + LEN];
    __shared__ alignas(8)   unsigned long long mbar[NST];

    const int tid  = threadIdx.x;
    const int wid  = tid >> 5;
    const int lane = tid & 31;
    const int row  = blockIdx.x;
    const int ch   = row & (DIM - 1);            // row = n*DIM + c

    const float* __restrict__ xrow = x   + (size_t)row * LEN;
    float*       __restrict__ orow = out + (size_t)row * LEN;

    // ---- init barriers + zero the 16-float left pad ----
    if (tid < NST) mbar_init(smem_u32(&mbar[tid]), 1);
    if (tid < KSZ / 4) {
        float4 z = make_float4(0.f, 0.f, 0.f, 0.f);
        *reinterpret_cast<float4*>(&buf[4 * tid]) = z;
    }
    __syncthreads();

    // ---- producer: lane 0 of warp s issues stage s (4KB, aligned, no overlap) ----
    if (lane == 0) {
        asm volatile("fence.proxy.async.shared::cta;" ::: "memory");
        const uint64_t pol = l2_evict_first_policy();
        const int s = wid;
        mbar_expect_tx(smem_u32(&mbar[s]), TILEB);
        bulk_g2s_hint(smem_u32(&buf[KSZ + s * TILE]), xrow + s * TILE,
                      TILEB, smem_u32(&mbar[s]), pol);
    }

    // ---- weights + bias (warp-uniform, overlaps TMA) ----
    float wr[KSZ];
    const float4* w4 = reinterpret_cast<const float4*>(w + ch * KSZ);
    #pragma unroll
    for (int q = 0; q < 4; q++) {
        float4 t = w4[q];
        wr[4 * q + 0] = t.x; wr[4 * q + 1] = t.y;
        wr[4 * q + 2] = t.z; wr[4 * q + 3] = t.w;
    }
    const float b = bias[ch];

    // ---- consume stages in order; halo of stage s is the tail of stage s-1,
    //      whose barrier was waited in the previous iteration ----
    #pragma unroll
    for (int s = 0; s < NST; s++) {
        mbar_wait_parity0(smem_u32(&mbar[s]));

        // window r[i] = xrow[s*TILE - 16 + 4*tid + i] = buf[s*TILE + 4*tid + i]
        float r[OPT + KSZ];
        const float4* sp = reinterpret_cast<const float4*>(&buf[s * TILE + 4 * tid]);
        #pragma unroll
        for (int q = 0; q < 5; q++) {
            float4 v = sp[q];
            r[4 * q + 0] = v.x; r[4 * q + 1] = v.y;
            r[4 * q + 2] = v.z; r[4 * q + 3] = v.w;
        }

        float acc[OPT];
        #pragma unroll
        for (int m = 0; m < OPT; m++) {
            float a = b;
            #pragma unroll
            for (int k = 0; k < KSZ; k++)
                a = fmaf(wr[k], r[m + 1 + k], a);
            acc[m] = a;
        }

        stg_cs_v4(orow + s * TILE + 4 * tid, acc[0], acc[1], acc[2], acc[3]);
    }
}

extern "C" void kernel_launch(void* const* d_in, const int* in_sizes, int n_in,
                              void* d_out, int out_size)
{
    const float* x    = (const float*)d_in[0];
    const float* w    = (const float*)d_in[1];
    const float* bias = (const float*)d_in[2];
    float* out        = (float*)d_out;

    const int blocks = 4 * DIM;                  // 8192 rows
    causal_conv1d_kernel<<<blocks, BLOCK>>>(x, w, bias, out);
}